// round 1
// baseline (speedup 1.0000x reference)
#include <cuda_runtime.h>
#include <math.h>

// Problem dims
#define B_ 32
#define T_ 512
#define D_ 2048
#define H_ 128
#define G_ 512   // 4*H gates

// Scratch (static device arrays: allocation-free rule)
__device__ float g_xp[(size_t)B_ * T_ * G_];   // forward input projection [B*T, G], 32 MB
__device__ float g_gb[B_ * G_];                // backward-dir one-step gate pre-activations
__device__ float g_hf[B_ * H_];                // forward final hidden state

__device__ __forceinline__ float sigf(float x) { return 1.0f / (1.0f + __expf(-x)); }

// ---------------------------------------------------------------------------
// Kernel 1: xp[m,g] = sum_k X[m,k]*W[g,k] + bih[g] + bhh[g]
// M=16384, N=512, K=2048. Classic 128x128x8 SGEMM, 256 threads, 8x8 microtile,
// smem double buffered. Grid: (N/128=4, M/128=128).
// ---------------------------------------------------------------------------
__global__ __launch_bounds__(256, 2) void sgemm_xp(
    const float* __restrict__ X,
    const float* __restrict__ W,
    const float* __restrict__ bih,
    const float* __restrict__ bhh)
{
    __shared__ float As[2][8][128];
    __shared__ float Bs[2][8][128];

    const int tid  = threadIdx.x;
    const int m0   = blockIdx.y * 128;
    const int n0   = blockIdx.x * 128;
    const int lrow = tid >> 1;            // 0..127
    const int lcol = (tid & 1) << 2;      // 0 or 4
    const int ty   = tid >> 4;            // 0..15
    const int tx   = tid & 15;            // 0..15

    const float* Xg = X + (size_t)(m0 + lrow) * D_ + lcol;
    const float* Wg = W + (size_t)(n0 + lrow) * D_ + lcol;

    float acc[8][8];
#pragma unroll
    for (int i = 0; i < 8; i++)
#pragma unroll
        for (int j = 0; j < 8; j++) acc[i][j] = 0.0f;

    // preload first K-tile
    float4 xa = *(const float4*)Xg;
    float4 wa = *(const float4*)Wg;
    As[0][lcol + 0][lrow] = xa.x; As[0][lcol + 1][lrow] = xa.y;
    As[0][lcol + 2][lrow] = xa.z; As[0][lcol + 3][lrow] = xa.w;
    Bs[0][lcol + 0][lrow] = wa.x; Bs[0][lcol + 1][lrow] = wa.y;
    Bs[0][lcol + 2][lrow] = wa.z; Bs[0][lcol + 3][lrow] = wa.w;
    __syncthreads();

    int buf = 0;
    for (int k0 = 8; k0 <= D_; k0 += 8) {
        const bool more = (k0 < D_);
        if (more) {
            xa = *(const float4*)(Xg + k0);
            wa = *(const float4*)(Wg + k0);
        }
#pragma unroll
        for (int kk = 0; kk < 8; kk++) {
            float4 a0 = *(const float4*)&As[buf][kk][ty * 8];
            float4 a1 = *(const float4*)&As[buf][kk][ty * 8 + 4];
            float4 b0 = *(const float4*)&Bs[buf][kk][tx * 8];
            float4 b1 = *(const float4*)&Bs[buf][kk][tx * 8 + 4];
            float av[8] = {a0.x, a0.y, a0.z, a0.w, a1.x, a1.y, a1.z, a1.w};
            float bv[8] = {b0.x, b0.y, b0.z, b0.w, b1.x, b1.y, b1.z, b1.w};
#pragma unroll
            for (int i = 0; i < 8; i++)
#pragma unroll
                for (int j = 0; j < 8; j++)
                    acc[i][j] = fmaf(av[i], bv[j], acc[i][j]);
        }
        if (!more) break;
        const int nb = buf ^ 1;
        As[nb][lcol + 0][lrow] = xa.x; As[nb][lcol + 1][lrow] = xa.y;
        As[nb][lcol + 2][lrow] = xa.z; As[nb][lcol + 3][lrow] = xa.w;
        Bs[nb][lcol + 0][lrow] = wa.x; Bs[nb][lcol + 1][lrow] = wa.y;
        Bs[nb][lcol + 2][lrow] = wa.z; Bs[nb][lcol + 3][lrow] = wa.w;
        __syncthreads();
        buf = nb;
    }

    // epilogue: add bias, store
    const int g0 = n0 + tx * 8;
    float bias[8];
#pragma unroll
    for (int j = 0; j < 8; j++) bias[j] = bih[g0 + j] + bhh[g0 + j];
#pragma unroll
    for (int i = 0; i < 8; i++) {
        const int m = m0 + ty * 8 + i;
        float4 v0 = make_float4(acc[i][0] + bias[0], acc[i][1] + bias[1],
                                acc[i][2] + bias[2], acc[i][3] + bias[3]);
        float4 v1 = make_float4(acc[i][4] + bias[4], acc[i][5] + bias[5],
                                acc[i][6] + bias[6], acc[i][7] + bias[7]);
        *(float4*)&g_xp[(size_t)m * G_ + g0]     = v0;
        *(float4*)&g_xp[(size_t)m * G_ + g0 + 4] = v1;
    }
}

// ---------------------------------------------------------------------------
// Kernel 2: backward direction, single step at t=T-1, h0=c0=0:
// gate pre-activations gb[b,g] = sum_k x[b,T-1,k]*W_ih_b[g,k] + bih[g] + bhh[g]
// Grid (32, 16), 256 threads; warp computes 4 gates via warp-reduced dots.
// ---------------------------------------------------------------------------
__global__ __launch_bounds__(256) void bwd_gates(
    const float* __restrict__ X,
    const float* __restrict__ W,
    const float* __restrict__ bih,
    const float* __restrict__ bhh)
{
    const int b  = blockIdx.x;
    const int gy = blockIdx.y;
    __shared__ float xs[D_];
    const float* xrow = X + ((size_t)b * T_ + (T_ - 1)) * D_;
    for (int i = threadIdx.x; i < D_; i += 256) xs[i] = xrow[i];
    __syncthreads();

    const int w    = threadIdx.x >> 5;
    const int lane = threadIdx.x & 31;
#pragma unroll
    for (int q = 0; q < 4; q++) {
        const int g = gy * 32 + w * 4 + q;
        const float* wr = W + (size_t)g * D_;
        float s = 0.0f;
        for (int k = lane; k < D_; k += 32) s = fmaf(wr[k], xs[k], s);
#pragma unroll
        for (int off = 16; off > 0; off >>= 1)
            s += __shfl_down_sync(0xffffffffu, s, off);
        if (lane == 0) g_gb[b * G_ + g] = s + bih[g] + bhh[g];
    }
}

// ---------------------------------------------------------------------------
// Kernel 3: forward LSTM recurrence. One CTA per batch element, 512 threads;
// thread g owns gate row g of W_hh (128 weights register-resident as 64 packed
// bf16 pairs; fp32 accumulation via shift-expand). c lives in registers of
// threads 0..127; h in smem. 512 sequential steps.
// ---------------------------------------------------------------------------
__global__ __launch_bounds__(512, 1) void lstm_fwd(const float* __restrict__ W_hh)
{
    const int b = blockIdx.x;
    const int g = threadIdx.x;

    __shared__ __align__(16) float h_sh[H_];
    __shared__ float acts[G_];

    // pack W_hh row g: two bf16 (round-half-up) per uint32
    unsigned wpk[64];
    const float* wr = W_hh + (size_t)g * H_;
#pragma unroll
    for (int j = 0; j < 64; j++) {
        unsigned u0 = (__float_as_uint(wr[2 * j])     + 0x8000u) >> 16;
        unsigned u1 = (__float_as_uint(wr[2 * j + 1]) + 0x8000u) & 0xFFFF0000u;
        wpk[j] = u1 | u0;
    }

    if (g < H_) h_sh[g] = 0.0f;
    float c = 0.0f;
    __syncthreads();

    const float* xpb = g_xp + (size_t)b * T_ * G_ + g;
    float xcur = __ldg(xpb);

    for (int t = 0; t < T_; t++) {
        const float xnext = (t < T_ - 1) ? __ldg(xpb + (size_t)(t + 1) * G_) : 0.0f;

        float accum = xcur;
        const float2* h2 = (const float2*)h_sh;
#pragma unroll
        for (int j = 0; j < 64; j++) {
            const float2 hv = h2[j];
            const unsigned u = wpk[j];
            accum = fmaf(__uint_as_float(u << 16),          hv.x, accum);
            accum = fmaf(__uint_as_float(u & 0xFFFF0000u),  hv.y, accum);
        }

        // gate activation: sections i,f,o -> sigmoid ; section g -> tanh
        float a;
        if ((g >> 7) == 2) a = tanhf(accum);
        else               a = sigf(accum);
        acts[g] = a;
        __syncthreads();

        if (g < H_) {
            c = acts[H_ + g] * c + acts[g] * acts[2 * H_ + g];
            h_sh[g] = acts[3 * H_ + g] * tanhf(c);
        }
        xcur = xnext;
        __syncthreads();
    }

    if (g < H_) g_hf[b * H_ + g] = h_sh[g];
}

// ---------------------------------------------------------------------------
// Kernel 4: head. One CTA per batch element.
// last = [h_f, h_b(one backward step)]; 3 fc layers; softmax.
// ---------------------------------------------------------------------------
__global__ __launch_bounds__(256) void head_kernel(
    const float* __restrict__ W1, const float* __restrict__ b1,
    const float* __restrict__ W2, const float* __restrict__ b2,
    const float* __restrict__ W3, const float* __restrict__ b3,
    float* __restrict__ out)
{
    const int b = blockIdx.x;
    const int j = threadIdx.x;
    __shared__ float last[256];
    __shared__ float x1[256];
    __shared__ float x2[64];
    __shared__ float lg[11];
    __shared__ float inv_sum;

    if (j < H_) {
        last[j] = g_hf[b * H_ + j];
        const float gi = g_gb[b * G_ + j];
        const float gg = g_gb[b * G_ + 2 * H_ + j];
        const float go = g_gb[b * G_ + 3 * H_ + j];
        const float cb = sigf(gi) * tanhf(gg);
        last[H_ + j] = sigf(go) * tanhf(cb);
    }
    __syncthreads();

    {   // fc1: 256 -> 256
        float s = b1[j];
        const float* w = W1 + (size_t)j * 256;
#pragma unroll 8
        for (int k = 0; k < 256; k++) s = fmaf(w[k], last[k], s);
        x1[j] = s;
    }
    __syncthreads();

    if (j < 64) {   // fc2: 256 -> 64
        float s = b2[j];
        const float* w = W2 + (size_t)j * 256;
#pragma unroll 8
        for (int k = 0; k < 256; k++) s = fmaf(w[k], x1[k], s);
        x2[j] = s;
    }
    __syncthreads();

    if (j < 11) {   // fc3: 64 -> 11
        float s = b3[j];
        const float* w = W3 + (size_t)j * 64;
#pragma unroll
        for (int k = 0; k < 64; k++) s = fmaf(w[k], x2[k], s);
        lg[j] = s;
    }
    __syncthreads();

    if (j == 0) {
        float mx = lg[0];
        for (int k = 1; k < 11; k++) mx = fmaxf(mx, lg[k]);
        float sum = 0.0f;
        for (int k = 0; k < 11; k++) { const float e = __expf(lg[k] - mx); lg[k] = e; sum += e; }
        inv_sum = 1.0f / sum;
    }
    __syncthreads();
    if (j < 11) out[b * 11 + j] = lg[j] * inv_sum;
}

// ---------------------------------------------------------------------------
extern "C" void kernel_launch(void* const* d_in, const int* in_sizes, int n_in,
                              void* d_out, int out_size)
{
    const float* X      = (const float*)d_in[0];
    const float* W_ih_f = (const float*)d_in[1];
    const float* W_hh_f = (const float*)d_in[2];
    const float* b_ih_f = (const float*)d_in[3];
    const float* b_hh_f = (const float*)d_in[4];
    const float* W_ih_b = (const float*)d_in[5];
    // d_in[6] = W_hh_b: provably unused (backward dir contributes only its first
    // step from h0=0, so h @ W_hh_b^T == 0).
    const float* b_ih_b = (const float*)d_in[7];
    const float* b_hh_b = (const float*)d_in[8];
    const float* W1 = (const float*)d_in[9];  const float* b1 = (const float*)d_in[10];
    const float* W2 = (const float*)d_in[11]; const float* b2 = (const float*)d_in[12];
    const float* W3 = (const float*)d_in[13]; const float* b3 = (const float*)d_in[14];
    float* out = (float*)d_out;

    sgemm_xp <<<dim3(4, 128), 256>>>(X, W_ih_f, b_ih_f, b_hh_f);
    bwd_gates<<<dim3(32, 16), 256>>>(X, W_ih_b, b_ih_b, b_hh_b);
    lstm_fwd <<<32, 512>>>(W_hh_f);
    head_kernel<<<32, 256>>>(W1, b1, W2, b2, W3, b3, out);
}

// round 4
// speedup vs baseline: 1.4083x; 1.4083x over previous
#include <cuda_runtime.h>
#include <cuda_bf16.h>
#include <stdint.h>
#include <math.h>

// Problem dims
#define B_ 32
#define T_ 512
#define D_ 2048
#define H_ 128
#define G_ 512
#define M_ (B_ * T_)   // 16384

// ---------------------------------------------------------------------------
// Static device scratch (allocation-free rule)
// ---------------------------------------------------------------------------
__device__ float          g_xp[(size_t)M_ * G_];     // 32 MB
__device__ float          g_gb[B_ * G_];
__device__ float          g_hf[B_ * H_];
__device__ __nv_bfloat16  g_Xhi[(size_t)M_ * D_];    // 64 MB
__device__ __nv_bfloat16  g_Xlo[(size_t)M_ * D_];    // 64 MB
__device__ __nv_bfloat16  g_Whi[(size_t)G_ * D_];    // 2 MB
__device__ __nv_bfloat16  g_Wlo[(size_t)G_ * D_];    // 2 MB

__device__ __forceinline__ float sigf(float x) { return 1.0f / (1.0f + __expf(-x)); }

__device__ __forceinline__ unsigned smem_u32(const void* p) {
    unsigned a;
    asm("{ .reg .u64 t; cvta.to.shared.u64 t, %1; cvt.u32.u64 %0, t; }" : "=r"(a) : "l"(p));
    return a;
}
__device__ __forceinline__ void cpasync16(unsigned dst, const void* src) {
    asm volatile("cp.async.cg.shared.global [%0], [%1], 16;" :: "r"(dst), "l"(src));
}
__device__ __forceinline__ void ldsm4(unsigned* r, unsigned a) {
    asm volatile("ldmatrix.sync.aligned.m8n8.x4.shared.b16 {%0,%1,%2,%3}, [%4];"
        : "=r"(r[0]), "=r"(r[1]), "=r"(r[2]), "=r"(r[3]) : "r"(a));
}
__device__ __forceinline__ void mma16816(float* c, const unsigned* a, const unsigned* b) {
    asm volatile("mma.sync.aligned.m16n8k16.row.col.f32.bf16.bf16.f32 "
        "{%0,%1,%2,%3}, {%4,%5,%6,%7}, {%8,%9}, {%0,%1,%2,%3};"
        : "+f"(c[0]), "+f"(c[1]), "+f"(c[2]), "+f"(c[3])
        : "r"(a[0]), "r"(a[1]), "r"(a[2]), "r"(a[3]), "r"(b[0]), "r"(b[1]));
}

// ---------------------------------------------------------------------------
// Kernel A: split fp32 -> (hi, lo) bf16, vectorized x4
// ---------------------------------------------------------------------------
__global__ __launch_bounds__(256) void split_bf16(
    const float* __restrict__ src, __nv_bfloat16* __restrict__ hi,
    __nv_bfloat16* __restrict__ lo, int n4)
{
    int i = blockIdx.x * blockDim.x + threadIdx.x;
    if (i >= n4) return;
    float4 v = ((const float4*)src)[i];
    __nv_bfloat16 h0 = __float2bfloat16(v.x), h1 = __float2bfloat16(v.y);
    __nv_bfloat16 h2 = __float2bfloat16(v.z), h3 = __float2bfloat16(v.w);
    float r0 = v.x - __bfloat162float(h0), r1 = v.y - __bfloat162float(h1);
    float r2 = v.z - __bfloat162float(h2), r3 = v.w - __bfloat162float(h3);
    __nv_bfloat162* hp = (__nv_bfloat162*)hi;
    __nv_bfloat162* lp = (__nv_bfloat162*)lo;
    hp[2 * i]     = __halves2bfloat162(h0, h1);
    hp[2 * i + 1] = __halves2bfloat162(h2, h3);
    lp[2 * i]     = __floats2bfloat162_rn(r0, r1);
    lp[2 * i + 1] = __floats2bfloat162_rn(r2, r3);
}

// ---------------------------------------------------------------------------
// Kernel B: mma.sync bf16 GEMM  xp[m,g] = X[m,:].W[g,:] + bih[g] + bhh[g]
// 3-term split across an extended K loop (192 iterations of BK=32):
//   term 0: Xhi*Whi, term 1: Xhi*Wlo, term 2: Xlo*Whi
// BM=128, BN=128, 256 thr (8 warps, 2x4 layout of 64x32 warp tiles),
// cp.async double buffer, 80B-stride padded smem rows (ldmatrix conflict-free).
// Grid: (G/128=4, M/128=128).
// ---------------------------------------------------------------------------
#define NIT 192
#define STG 20480   // A 128*80 + B 128*80 bytes

__global__ __launch_bounds__(256, 2) void gemm_mma(
    const __nv_bfloat16* __restrict__ Xhi, const __nv_bfloat16* __restrict__ Xlo,
    const __nv_bfloat16* __restrict__ Whi, const __nv_bfloat16* __restrict__ Wlo,
    const float* __restrict__ bih, const float* __restrict__ bhh)
{
    __shared__ __align__(16) char sm[2 * STG];
    const int tid = threadIdx.x;
    const int wid = tid >> 5, lane = tid & 31;
    const int m0 = blockIdx.y * 128;
    const int n0 = blockIdx.x * 128;

    // loader mapping: thread tid covers (row = tid>>2, 8 bf16 at col (tid&3)*8),
    // plus a second chunk 64 rows below.
    const int ar0 = tid >> 2, ac0 = tid & 3;
    const size_t aoff = (size_t)(m0 + ar0) * D_ + ac0 * 8;
    const size_t boff = (size_t)(n0 + ar0) * D_ + ac0 * 8;
    const unsigned sdst0 = (unsigned)(ar0 * 80 + ac0 * 16);
    const unsigned sdst1 = sdst0 + 64 * 80;
    const unsigned smb = smem_u32(sm);

    const __nv_bfloat16* Aterm[3] = {Xhi, Xhi, Xlo};
    const __nv_bfloat16* Bterm[3] = {Whi, Wlo, Whi};

    // warp tile: 64 rows x 32 cols
    const int m_base = (wid & 1) * 64;
    const int n_base = (wid >> 1) * 32;
    // ldmatrix lane offsets (bytes)
    const unsigned a_lm = (unsigned)((lane & 15) * 80 + (lane >> 4) * 16);
    const unsigned b_lm = (unsigned)(((lane & 7) + (lane >> 4) * 8) * 80 + ((lane >> 3) & 1) * 16);

    float acc[4][4][4];
#pragma unroll
    for (int i = 0; i < 4; i++)
#pragma unroll
        for (int j = 0; j < 4; j++)
#pragma unroll
            for (int k = 0; k < 4; k++) acc[i][j][k] = 0.0f;

    auto load_stage = [&](int it, int s) {
        const int term = it >> 6;
        const int kk = (it & 63) * 32;
        const __nv_bfloat16* A  = Aterm[term] + kk;
        const __nv_bfloat16* Bt = Bterm[term] + kk;
        const unsigned sa  = smb + s * STG;
        const unsigned sbb = sa + 10240;
        cpasync16(sa + sdst0,  A + aoff);
        cpasync16(sa + sdst1,  A + aoff + (size_t)64 * D_);
        cpasync16(sbb + sdst0, Bt + boff);
        cpasync16(sbb + sdst1, Bt + boff + (size_t)64 * D_);
        asm volatile("cp.async.commit_group;");
    };

    load_stage(0, 0);
    for (int it = 0; it < NIT; it++) {
        const int s = it & 1;
        if (it + 1 < NIT) {
            load_stage(it + 1, s ^ 1);
            asm volatile("cp.async.wait_group 1;");
        } else {
            asm volatile("cp.async.wait_group 0;");
        }
        __syncthreads();

        const unsigned saA = smb + s * STG;
        const unsigned saB = saA + 10240;
#pragma unroll
        for (int ks = 0; ks < 2; ks++) {
            unsigned af[4][4], bfr[2][4];
#pragma unroll
            for (int mt = 0; mt < 4; mt++)
                ldsm4(af[mt], saA + (unsigned)((m_base + mt * 16) * 80 + ks * 32) + a_lm);
#pragma unroll
            for (int nb = 0; nb < 2; nb++)
                ldsm4(bfr[nb], saB + (unsigned)((n_base + nb * 16) * 80 + ks * 32) + b_lm);
#pragma unroll
            for (int mt = 0; mt < 4; mt++)
#pragma unroll
                for (int nt = 0; nt < 4; nt++)
                    mma16816(acc[mt][nt], af[mt], &bfr[nt >> 1][(nt & 1) * 2]);
        }
        __syncthreads();
    }

    // epilogue: direct float2 stores with bias
    const int gid = lane >> 2, tg = lane & 3;
#pragma unroll
    for (int nt = 0; nt < 4; nt++) {
        const int col = n0 + n_base + nt * 8 + tg * 2;
        const float b0 = bih[col] + bhh[col];
        const float b1 = bih[col + 1] + bhh[col + 1];
#pragma unroll
        for (int mt = 0; mt < 4; mt++) {
            const int r0 = m0 + m_base + mt * 16 + gid;
            *(float2*)&g_xp[(size_t)r0 * G_ + col] =
                make_float2(acc[mt][nt][0] + b0, acc[mt][nt][1] + b1);
            *(float2*)&g_xp[(size_t)(r0 + 8) * G_ + col] =
                make_float2(acc[mt][nt][2] + b0, acc[mt][nt][3] + b1);
        }
    }
}

// ---------------------------------------------------------------------------
// Kernel C: backward direction, single step at t=T-1, h0=c0=0.
// ---------------------------------------------------------------------------
__global__ __launch_bounds__(256) void bwd_gates(
    const float* __restrict__ X, const float* __restrict__ W,
    const float* __restrict__ bih, const float* __restrict__ bhh)
{
    const int b  = blockIdx.x;
    const int gy = blockIdx.y;
    __shared__ float xs[D_];
    const float* xrow = X + ((size_t)b * T_ + (T_ - 1)) * D_;
    for (int i = threadIdx.x; i < D_; i += 256) xs[i] = xrow[i];
    __syncthreads();

    const int w = threadIdx.x >> 5, lane = threadIdx.x & 31;
#pragma unroll
    for (int q = 0; q < 4; q++) {
        const int g = gy * 32 + w * 4 + q;
        const float* wr = W + (size_t)g * D_;
        float s = 0.0f;
        for (int k = lane; k < D_; k += 32) s = fmaf(wr[k], xs[k], s);
#pragma unroll
        for (int off = 16; off > 0; off >>= 1) s += __shfl_down_sync(0xffffffffu, s, off);
        if (lane == 0) g_gb[b * G_ + g] = s + bih[g] + bhh[g];
    }
}

// ---------------------------------------------------------------------------
// Kernel D: forward LSTM recurrence.
// 512 threads (one per gate), 1 CTA per batch element.
// First 64 W_hh weights raw f32 in regs (no unpack ALU), last 64 as packed
// bf16 pairs. h via float4 LDS, 4 independent accumulators.
// ---------------------------------------------------------------------------
__global__ __launch_bounds__(512, 1) void lstm_fwd(const float* __restrict__ W_hh)
{
    const int b = blockIdx.x;
    const int g = threadIdx.x;

    __shared__ __align__(16) float h_sh[H_];
    __shared__ float acts[G_];

    float    wf[64];
    unsigned wpk[32];
    const float* wr = W_hh + (size_t)g * H_;
#pragma unroll
    for (int j = 0; j < 64; j++) wf[j] = wr[j];
#pragma unroll
    for (int j = 0; j < 32; j++) {
        unsigned u0 = (__float_as_uint(wr[64 + 2 * j])     + 0x8000u) >> 16;
        unsigned u1 = (__float_as_uint(wr[64 + 2 * j + 1]) + 0x8000u) & 0xFFFF0000u;
        wpk[j] = u1 | u0;
    }

    if (g < H_) h_sh[g] = 0.0f;
    float c = 0.0f;
    __syncthreads();

    const float* xpb = g_xp + (size_t)b * T_ * G_ + g;
    float xcur = __ldg(xpb);

    for (int t = 0; t < T_; t++) {
        const float xnext = (t < T_ - 1) ? __ldg(xpb + (size_t)(t + 1) * G_) : 0.0f;

        float a0 = xcur, a1 = 0.0f, a2 = 0.0f, a3 = 0.0f;
        const float4* h4 = (const float4*)h_sh;
#pragma unroll
        for (int j = 0; j < 16; j++) {          // k = 0..63 : f32 weights
            const float4 hv = h4[j];
            a0 = fmaf(wf[4 * j],     hv.x, a0);
            a1 = fmaf(wf[4 * j + 1], hv.y, a1);
            a2 = fmaf(wf[4 * j + 2], hv.z, a2);
            a3 = fmaf(wf[4 * j + 3], hv.w, a3);
        }
#pragma unroll
        for (int j = 0; j < 16; j++) {          // k = 64..127 : packed bf16
            const float4 hv = h4[16 + j];
            const unsigned ua = wpk[2 * j], ub = wpk[2 * j + 1];
            a0 = fmaf(__uint_as_float(ua << 16),          hv.x, a0);
            a1 = fmaf(__uint_as_float(ua & 0xFFFF0000u),  hv.y, a1);
            a2 = fmaf(__uint_as_float(ub << 16),          hv.z, a2);
            a3 = fmaf(__uint_as_float(ub & 0xFFFF0000u),  hv.w, a3);
        }
        const float accum = (a0 + a1) + (a2 + a3);

        float a;
        if ((g >> 7) == 2) a = tanhf(accum);    // g-section
        else               a = sigf(accum);     // i, f, o
        acts[g] = a;
        __syncthreads();

        if (g < H_) {
            c = acts[H_ + g] * c + acts[g] * acts[2 * H_ + g];
            h_sh[g] = acts[3 * H_ + g] * tanhf(c);
        }
        xcur = xnext;
        __syncthreads();
    }

    if (g < H_) g_hf[b * H_ + g] = h_sh[g];
}

// ---------------------------------------------------------------------------
// Kernel E: head — warp-cooperative, coalesced weight reads.
// ---------------------------------------------------------------------------
__global__ __launch_bounds__(256) void head_kernel(
    const float* __restrict__ W1, const float* __restrict__ b1,
    const float* __restrict__ W2, const float* __restrict__ b2,
    const float* __restrict__ W3, const float* __restrict__ b3,
    float* __restrict__ out)
{
    const int b = blockIdx.x;
    const int tid = threadIdx.x, w = tid >> 5, l = tid & 31;
    __shared__ float last[256];
    __shared__ float x1[256];
    __shared__ float x2[64];
    __shared__ float lg[16];
    __shared__ float inv_sum;

    if (tid < 128) {
        last[tid] = g_hf[b * H_ + tid];
    } else {
        const int j = tid - 128;
        const float gi = g_gb[b * G_ + j];
        const float gg = g_gb[b * G_ + 2 * H_ + j];
        const float go = g_gb[b * G_ + 3 * H_ + j];
        last[tid] = sigf(go) * tanhf(sigf(gi) * tanhf(gg));
    }
    __syncthreads();

#pragma unroll 4
    for (int jj = 0; jj < 32; jj++) {           // fc1 256->256
        const int j = w * 32 + jj;
        const float* wr = W1 + (size_t)j * 256;
        float s = 0.0f;
#pragma unroll
        for (int q = 0; q < 8; q++) s = fmaf(wr[l + 32 * q], last[l + 32 * q], s);
#pragma unroll
        for (int off = 16; off > 0; off >>= 1) s += __shfl_xor_sync(0xffffffffu, s, off);
        if (l == 0) x1[j] = s + b1[j];
    }
    __syncthreads();

#pragma unroll
    for (int jj = 0; jj < 8; jj++) {            // fc2 256->64
        const int j = w * 8 + jj;
        const float* wr = W2 + (size_t)j * 256;
        float s = 0.0f;
#pragma unroll
        for (int q = 0; q < 8; q++) s = fmaf(wr[l + 32 * q], x1[l + 32 * q], s);
#pragma unroll
        for (int off = 16; off > 0; off >>= 1) s += __shfl_xor_sync(0xffffffffu, s, off);
        if (l == 0) x2[j] = s + b2[j];
    }
    __syncthreads();

    if (w == 0) {                               // fc3 64->11
        for (int j = 0; j < 11; j++) {
            const float* wr = W3 + (size_t)j * 64;
            float s = fmaf(wr[l], x2[l], 0.0f);
            s = fmaf(wr[l + 32], x2[l + 32], s);
#pragma unroll
            for (int off = 16; off > 0; off >>= 1) s += __shfl_xor_sync(0xffffffffu, s, off);
            if (l == 0) lg[j] = s + b3[j];
        }
    }
    __syncthreads();

    if (tid == 0) {
        float mx = lg[0];
        for (int k = 1; k < 11; k++) mx = fmaxf(mx, lg[k]);
        float sum = 0.0f;
        for (int k = 0; k < 11; k++) { const float e = __expf(lg[k] - mx); lg[k] = e; sum += e; }
        inv_sum = 1.0f / sum;
    }
    __syncthreads();
    if (tid < 11) out[b * 11 + tid] = lg[tid] * inv_sum;
}

// ---------------------------------------------------------------------------
extern "C" void kernel_launch(void* const* d_in, const int* in_sizes, int n_in,
                              void* d_out, int out_size)
{
    const float* X      = (const float*)d_in[0];
    const float* W_ih_f = (const float*)d_in[1];
    const float* W_hh_f = (const float*)d_in[2];
    const float* b_ih_f = (const float*)d_in[3];
    const float* b_hh_f = (const float*)d_in[4];
    const float* W_ih_b = (const float*)d_in[5];
    // d_in[6] = W_hh_b: unused (backward dir contributes only its first step from h0=0)
    const float* b_ih_b = (const float*)d_in[7];
    const float* b_hh_b = (const float*)d_in[8];
    const float* W1 = (const float*)d_in[9];  const float* b1 = (const float*)d_in[10];
    const float* W2 = (const float*)d_in[11]; const float* b2 = (const float*)d_in[12];
    const float* W3 = (const float*)d_in[13]; const float* b3 = (const float*)d_in[14];
    float* out = (float*)d_out;

    void *pXhi, *pXlo, *pWhi, *pWlo;
    cudaGetSymbolAddress(&pXhi, g_Xhi);
    cudaGetSymbolAddress(&pXlo, g_Xlo);
    cudaGetSymbolAddress(&pWhi, g_Whi);
    cudaGetSymbolAddress(&pWlo, g_Wlo);

    split_bf16<<<(M_ * D_ / 4 + 255) / 256, 256>>>(X, (__nv_bfloat16*)pXhi,
                                                   (__nv_bfloat16*)pXlo, M_ * D_ / 4);
    split_bf16<<<(G_ * D_ / 4 + 255) / 256, 256>>>(W_ih_f, (__nv_bfloat16*)pWhi,
                                                   (__nv_bfloat16*)pWlo, G_ * D_ / 4);
    gemm_mma<<<dim3(G_ / 128, M_ / 128), 256>>>((const __nv_bfloat16*)pXhi,
                                                (const __nv_bfloat16*)pXlo,
                                                (const __nv_bfloat16*)pWhi,
                                                (const __nv_bfloat16*)pWlo,
                                                b_ih_f, b_hh_f);
    bwd_gates<<<dim3(B_, 16), 256>>>(X, W_ih_b, b_ih_b, b_hh_b);
    lstm_fwd<<<B_, 512>>>(W_hh_f);
    head_kernel<<<B_, 256>>>(W1, b1, W2, b2, W3, b3, out);
}

// round 11
// speedup vs baseline: 1.7292x; 1.2278x over previous
#include <cuda_runtime.h>
#include <cuda_bf16.h>
#include <stdint.h>
#include <math.h>

// Problem dims
#define B_ 32
#define T_ 512
#define D_ 2048
#define H_ 128
#define G_ 512
#define M_ (B_ * T_)   // 16384

// Fused kernel geometry: EVERYTHING fits in one wave (148 SMs)
#define LSTM_BLKS 32
#define WORK_BLKS 116
#define FUSED_GRID (LSTM_BLKS + WORK_BLKS)   // 148
#define NTILES 256                            // 128 row-tiles x 2 col-tiles
#define NBWD 512

// GEMM tiling: BM=128, BN=256, BK=32, 3 terms -> 192 iterations
#define NIT 192
#define STAGE_B 30720          // A 128*80 + B 256*80
#define NSTAGE 3
#define FUSED_SMEM (NSTAGE * STAGE_B)   // 92160

// ---------------------------------------------------------------------------
// Static device scratch (allocation-free rule)
// ---------------------------------------------------------------------------
__device__ float          g_xp[(size_t)M_ * G_];     // 32 MB
__device__ float          g_gb[B_ * G_];
__device__ float          g_hf[B_ * H_];
__device__ int            g_flag[128];               // per row-tile readiness (count to 2)
__device__ __nv_bfloat16  g_Xhi[(size_t)M_ * D_];
__device__ __nv_bfloat16  g_Xlo[(size_t)M_ * D_];
__device__ __nv_bfloat16  g_Whi[(size_t)G_ * D_];
__device__ __nv_bfloat16  g_Wlo[(size_t)G_ * D_];

__device__ __forceinline__ float sigf(float x) { return 1.0f / (1.0f + __expf(-x)); }

__device__ __forceinline__ unsigned smem_u32(const void* p) {
    unsigned a;
    asm("{ .reg .u64 t; cvta.to.shared.u64 t, %1; cvt.u32.u64 %0, t; }" : "=r"(a) : "l"(p));
    return a;
}
__device__ __forceinline__ void cpasync16(unsigned dst, const void* src) {
    asm volatile("cp.async.cg.shared.global [%0], [%1], 16;" :: "r"(dst), "l"(src));
}
__device__ __forceinline__ void ldsm4(unsigned* r, unsigned a) {
    asm volatile("ldmatrix.sync.aligned.m8n8.x4.shared.b16 {%0,%1,%2,%3}, [%4];"
        : "=r"(r[0]), "=r"(r[1]), "=r"(r[2]), "=r"(r[3]) : "r"(a));
}
__device__ __forceinline__ void mma16816(float* c, const unsigned* a, const unsigned* b) {
    asm volatile("mma.sync.aligned.m16n8k16.row.col.f32.bf16.bf16.f32 "
        "{%0,%1,%2,%3}, {%4,%5,%6,%7}, {%8,%9}, {%0,%1,%2,%3};"
        : "+f"(c[0]), "+f"(c[1]), "+f"(c[2]), "+f"(c[3])
        : "r"(a[0]), "r"(a[1]), "r"(a[2]), "r"(a[3]), "r"(b[0]), "r"(b[1]));
}

// ---------------------------------------------------------------------------
__global__ void zero_flags() {
    if (threadIdx.x < 128) g_flag[threadIdx.x] = 0;
}

// ---------------------------------------------------------------------------
// split fp32 -> (hi, lo) bf16
// ---------------------------------------------------------------------------
__global__ __launch_bounds__(256) void split_bf16(
    const float* __restrict__ src, __nv_bfloat16* __restrict__ hi,
    __nv_bfloat16* __restrict__ lo, int n4)
{
    int i = blockIdx.x * blockDim.x + threadIdx.x;
    if (i >= n4) return;
    float4 v = ((const float4*)src)[i];
    __nv_bfloat16 h0 = __float2bfloat16(v.x), h1 = __float2bfloat16(v.y);
    __nv_bfloat16 h2 = __float2bfloat16(v.z), h3 = __float2bfloat16(v.w);
    float r0 = v.x - __bfloat162float(h0), r1 = v.y - __bfloat162float(h1);
    float r2 = v.z - __bfloat162float(h2), r3 = v.w - __bfloat162float(h3);
    __nv_bfloat162* hp = (__nv_bfloat162*)hi;
    __nv_bfloat162* lp = (__nv_bfloat162*)lo;
    hp[2 * i]     = __halves2bfloat162(h0, h1);
    hp[2 * i + 1] = __halves2bfloat162(h2, h3);
    lp[2 * i]     = __floats2bfloat162_rn(r0, r1);
    lp[2 * i + 1] = __floats2bfloat162_rn(r2, r3);
}

// ---------------------------------------------------------------------------
// Fused persistent kernel, grid = 148 (one wave, all blocks resident):
//   bid [0,32)    : lstm consumer (one batch element each)
//   bid [32,148)  : persistent gemm worker (tiles w, w+116, w+232),
//                   then bwd_gates tail chunks
// ---------------------------------------------------------------------------
__global__ __launch_bounds__(512, 1) void fused_main(
    const float* __restrict__ W_hh,
    const float* __restrict__ bih_f, const float* __restrict__ bhh_f,
    const float* __restrict__ X,
    const float* __restrict__ W_ih_b,
    const float* __restrict__ bih_b, const float* __restrict__ bhh_b)
{
    extern __shared__ __align__(16) char dyn_sm[];
    const int bid = blockIdx.x;
    const int tid = threadIdx.x;

    // ======================= LSTM role ====================================
    if (bid < LSTM_BLKS) {
        const int b = bid;
        const int g = tid;
        float* h_sh = (float*)dyn_sm;          // 128
        float* acts = h_sh + 128;              // 512

        float    wf[64];
        unsigned wpk[32];
        const float* wr = W_hh + (size_t)g * H_;
#pragma unroll
        for (int j = 0; j < 64; j++) wf[j] = wr[j];
#pragma unroll
        for (int j = 0; j < 32; j++) {
            unsigned u0 = (__float_as_uint(wr[64 + 2 * j])     + 0x8000u) >> 16;
            unsigned u1 = (__float_as_uint(wr[64 + 2 * j + 1]) + 0x8000u) & 0xFFFF0000u;
            wpk[j] = u1 | u0;
        }

        if (g < H_) h_sh[g] = 0.0f;
        float c = 0.0f;
        __syncthreads();

        for (int tc = 0; tc < 4; tc++) {
            // wait for both GEMM n-tiles of row-block (b*4 + tc); bounded spin
            if (tid == 0) {
                const int* fp = &g_flag[b * 4 + tc];
                int v, tries = 0;
                while (true) {
                    asm volatile("ld.acquire.gpu.global.b32 %0, [%1];" : "=r"(v) : "l"(fp));
                    if (v >= 2) break;
                    if (++tries > 3000000) break;   // fail loud (bad rel_err), never hang
                    __nanosleep(200);
                }
            }
            __syncthreads();

            const float* xpc = g_xp + ((size_t)b * T_ + tc * 128) * G_ + g;
            float xcur = xpc[0];
            for (int tt = 0; tt < 128; tt++) {
                const float xnext = (tt < 127) ? xpc[(size_t)(tt + 1) * G_] : 0.0f;

                float a0 = xcur, a1 = 0.0f, a2 = 0.0f, a3 = 0.0f;
                const float4* h4 = (const float4*)h_sh;
#pragma unroll
                for (int j = 0; j < 16; j++) {
                    const float4 hv = h4[j];
                    a0 = fmaf(wf[4 * j],     hv.x, a0);
                    a1 = fmaf(wf[4 * j + 1], hv.y, a1);
                    a2 = fmaf(wf[4 * j + 2], hv.z, a2);
                    a3 = fmaf(wf[4 * j + 3], hv.w, a3);
                }
#pragma unroll
                for (int j = 0; j < 16; j++) {
                    const float4 hv = h4[16 + j];
                    const unsigned ua = wpk[2 * j], ub = wpk[2 * j + 1];
                    a0 = fmaf(__uint_as_float(ua << 16),          hv.x, a0);
                    a1 = fmaf(__uint_as_float(ua & 0xFFFF0000u),  hv.y, a1);
                    a2 = fmaf(__uint_as_float(ub << 16),          hv.z, a2);
                    a3 = fmaf(__uint_as_float(ub & 0xFFFF0000u),  hv.w, a3);
                }
                const float accum = (a0 + a1) + (a2 + a3);

                float a;
                if ((g >> 7) == 2) a = tanhf(accum);
                else               a = sigf(accum);
                acts[g] = a;
                __syncthreads();

                if (g < H_) {
                    c = acts[H_ + g] * c + acts[g] * acts[2 * H_ + g];
                    h_sh[g] = acts[3 * H_ + g] * tanhf(c);
                }
                xcur = xnext;
                __syncthreads();
            }
        }
        if (g < H_) g_hf[b * H_ + g] = h_sh[g];
        return;
    }

    // ================== persistent GEMM worker role =======================
    {
        const int w = bid - LSTM_BLKS;        // 0..115
        const int wid = tid >> 5, lane = tid & 31;
        const unsigned smb = smem_u32(dyn_sm);

        // loader mapping (tile-independent parts)
        const int lrow = tid >> 2, lc16 = tid & 3;
        const unsigned sdA  = (unsigned)(lrow * 80 + lc16 * 16);
        const unsigned sdB0 = (unsigned)(10240 + lrow * 80 + lc16 * 16);
        const unsigned sdB1 = sdB0 + 128 * 80;

        const __nv_bfloat16* Aterm[3] = {g_Xhi, g_Xhi, g_Xlo};
        const __nv_bfloat16* Bterm[3] = {g_Whi, g_Wlo, g_Whi};

        // warp tile: 32 rows x 64 cols (16 warps in 4x4)
        const int m_base = (wid & 3) * 32;
        const int n_base = (wid >> 2) * 64;
        const unsigned a_lm = (unsigned)((lane & 15) * 80 + (lane >> 4) * 16);
        const unsigned b_lm = (unsigned)(((lane & 7) + (lane >> 4) * 8) * 80 + ((lane >> 3) & 1) * 16);

        for (int ti = w; ti < NTILES; ti += WORK_BLKS) {
            // t-chunk-major tile decode
            const int tc = ti >> 6;
            const int bb = (ti >> 1) & 31;
            const int nb = ti & 1;
            const int rb = bb * 4 + tc;
            const int m0 = rb * 128;
            const int n0 = nb * 256;

            const size_t aoff  = (size_t)(m0 + lrow) * D_ + lc16 * 8;
            const size_t boff0 = (size_t)(n0 + lrow) * D_ + lc16 * 8;
            const size_t boff1 = boff0 + (size_t)128 * D_;

            float acc[2][8][4];
#pragma unroll
            for (int i = 0; i < 2; i++)
#pragma unroll
                for (int j = 0; j < 8; j++)
#pragma unroll
                    for (int k = 0; k < 4; k++) acc[i][j][k] = 0.0f;

            auto load_stage = [&](int it, int s) {
                const int term = it >> 6;
                const int kk = (it & 63) * 32;
                const __nv_bfloat16* A  = Aterm[term] + kk;
                const __nv_bfloat16* Bt = Bterm[term] + kk;
                const unsigned sa = smb + s * STAGE_B;
                cpasync16(sa + sdA,  A + aoff);
                cpasync16(sa + sdB0, Bt + boff0);
                cpasync16(sa + sdB1, Bt + boff1);
                asm volatile("cp.async.commit_group;");
            };

            __syncthreads();   // smem handoff between tiles
            load_stage(0, 0);
            load_stage(1, 1);

            int sc = 0, sl = 2;
            for (int it = 0; it < NIT; it++) {
                if (it + 2 < NIT) asm volatile("cp.async.wait_group 1;");
                else              asm volatile("cp.async.wait_group 0;");
                __syncthreads();
                if (it + 2 < NIT) load_stage(it + 2, sl);

                const unsigned saA = smb + sc * STAGE_B;
                const unsigned saB = saA + 10240;
#pragma unroll
                for (int ks = 0; ks < 2; ks++) {
                    unsigned af[2][4], bfr[4][4];
#pragma unroll
                    for (int mt = 0; mt < 2; mt++)
                        ldsm4(af[mt], saA + (unsigned)((m_base + mt * 16) * 80 + ks * 32) + a_lm);
#pragma unroll
                    for (int nt4 = 0; nt4 < 4; nt4++)
                        ldsm4(bfr[nt4], saB + (unsigned)((n_base + nt4 * 16) * 80 + ks * 32) + b_lm);
#pragma unroll
                    for (int mt = 0; mt < 2; mt++)
#pragma unroll
                        for (int nt = 0; nt < 8; nt++)
                            mma16816(acc[mt][nt], af[mt], &bfr[nt >> 1][(nt & 1) * 2]);
                }
                sc = (sc == 2) ? 0 : sc + 1;
                sl = (sl == 2) ? 0 : sl + 1;
            }

            // epilogue with bias
            const int gid = lane >> 2, tg = lane & 3;
#pragma unroll
            for (int nt = 0; nt < 8; nt++) {
                const int col = n0 + n_base + nt * 8 + tg * 2;
                const float b0 = bih_f[col] + bhh_f[col];
                const float b1 = bih_f[col + 1] + bhh_f[col + 1];
#pragma unroll
                for (int mt = 0; mt < 2; mt++) {
                    const int r0 = m0 + m_base + mt * 16 + gid;
                    *(float2*)&g_xp[(size_t)r0 * G_ + col] =
                        make_float2(acc[mt][nt][0] + b0, acc[mt][nt][1] + b1);
                    *(float2*)&g_xp[(size_t)(r0 + 8) * G_ + col] =
                        make_float2(acc[mt][nt][2] + b0, acc[mt][nt][3] + b1);
                }
            }

            __threadfence();
            __syncthreads();
            if (tid == 0) atomicAdd(&g_flag[rb], 1);
        }

        // ---------------- bwd_gates tail work -----------------------------
        float* xs = (float*)dyn_sm;            // 2048 floats (smem free after GEMM)
        for (int lb = w; lb < NBWD; lb += WORK_BLKS) {
            const int b  = lb >> 4;
            const int gy = lb & 15;
            __syncthreads();                   // protect previous xs readers
            const float* xrow = X + ((size_t)b * T_ + (T_ - 1)) * D_;
            for (int i = tid; i < D_; i += 512) xs[i] = xrow[i];
            __syncthreads();

            const int ww = tid >> 5, lane2 = tid & 31;
#pragma unroll
            for (int q = 0; q < 2; q++) {
                const int g = gy * 32 + ww * 2 + q;
                const float* wr2 = W_ih_b + (size_t)g * D_;
                float s = 0.0f;
                for (int k = lane2; k < D_; k += 32) s = fmaf(wr2[k], xs[k], s);
#pragma unroll
                for (int off = 16; off > 0; off >>= 1) s += __shfl_down_sync(0xffffffffu, s, off);
                if (lane2 == 0) g_gb[b * G_ + g] = s + bih_b[g] + bhh_b[g];
            }
        }
        return;
    }
}

// ---------------------------------------------------------------------------
// head — warp-cooperative MLP + softmax
// ---------------------------------------------------------------------------
__global__ __launch_bounds__(256) void head_kernel(
    const float* __restrict__ W1, const float* __restrict__ b1,
    const float* __restrict__ W2, const float* __restrict__ b2,
    const float* __restrict__ W3, const float* __restrict__ b3,
    float* __restrict__ out)
{
    const int b = blockIdx.x;
    const int tid = threadIdx.x, w = tid >> 5, l = tid & 31;
    __shared__ float last[256];
    __shared__ float x1[256];
    __shared__ float x2[64];
    __shared__ float lg[16];
    __shared__ float inv_sum;

    if (tid < 128) {
        last[tid] = g_hf[b * H_ + tid];
    } else {
        const int j = tid - 128;
        const float gi = g_gb[b * G_ + j];
        const float gg = g_gb[b * G_ + 2 * H_ + j];
        const float go = g_gb[b * G_ + 3 * H_ + j];
        last[tid] = sigf(go) * tanhf(sigf(gi) * tanhf(gg));
    }
    __syncthreads();

#pragma unroll 4
    for (int jj = 0; jj < 32; jj++) {
        const int j = w * 32 + jj;
        const float* wr = W1 + (size_t)j * 256;
        float s = 0.0f;
#pragma unroll
        for (int q = 0; q < 8; q++) s = fmaf(wr[l + 32 * q], last[l + 32 * q], s);
#pragma unroll
        for (int off = 16; off > 0; off >>= 1) s += __shfl_xor_sync(0xffffffffu, s, off);
        if (l == 0) x1[j] = s + b1[j];
    }
    __syncthreads();

#pragma unroll
    for (int jj = 0; jj < 8; jj++) {
        const int j = w * 8 + jj;
        const float* wr = W2 + (size_t)j * 256;
        float s = 0.0f;
#pragma unroll
        for (int q = 0; q < 8; q++) s = fmaf(wr[l + 32 * q], x1[l + 32 * q], s);
#pragma unroll
        for (int off = 16; off > 0; off >>= 1) s += __shfl_xor_sync(0xffffffffu, s, off);
        if (l == 0) x2[j] = s + b2[j];
    }
    __syncthreads();

    if (w == 0) {
        for (int j = 0; j < 11; j++) {
            const float* wr = W3 + (size_t)j * 64;
            float s = fmaf(wr[l], x2[l], 0.0f);
            s = fmaf(wr[l + 32], x2[l + 32], s);
#pragma unroll
            for (int off = 16; off > 0; off >>= 1) s += __shfl_xor_sync(0xffffffffu, s, off);
            if (l == 0) lg[j] = s + b3[j];
        }
    }
    __syncthreads();

    if (tid == 0) {
        float mx = lg[0];
        for (int k = 1; k < 11; k++) mx = fmaxf(mx, lg[k]);
        float sum = 0.0f;
        for (int k = 0; k < 11; k++) { const float e = __expf(lg[k] - mx); lg[k] = e; sum += e; }
        inv_sum = 1.0f / sum;
    }
    __syncthreads();
    if (tid < 11) out[b * 11 + tid] = lg[tid] * inv_sum;
}

// ---------------------------------------------------------------------------
extern "C" void kernel_launch(void* const* d_in, const int* in_sizes, int n_in,
                              void* d_out, int out_size)
{
    const float* X      = (const float*)d_in[0];
    const float* W_ih_f = (const float*)d_in[1];
    const float* W_hh_f = (const float*)d_in[2];
    const float* b_ih_f = (const float*)d_in[3];
    const float* b_hh_f = (const float*)d_in[4];
    const float* W_ih_b = (const float*)d_in[5];
    // d_in[6] = W_hh_b: unused (backward dir contributes only its first step from h0=0)
    const float* b_ih_b = (const float*)d_in[7];
    const float* b_hh_b = (const float*)d_in[8];
    const float* W1 = (const float*)d_in[9];  const float* b1 = (const float*)d_in[10];
    const float* W2 = (const float*)d_in[11]; const float* b2 = (const float*)d_in[12];
    const float* W3 = (const float*)d_in[13]; const float* b3 = (const float*)d_in[14];
    float* out = (float*)d_out;

    void *pXhi, *pXlo, *pWhi, *pWlo;
    cudaGetSymbolAddress(&pXhi, g_Xhi);
    cudaGetSymbolAddress(&pXlo, g_Xlo);
    cudaGetSymbolAddress(&pWhi, g_Whi);
    cudaGetSymbolAddress(&pWlo, g_Wlo);

    cudaFuncSetAttribute(fused_main, cudaFuncAttributeMaxDynamicSharedMemorySize, FUSED_SMEM);

    zero_flags<<<1, 128>>>();
    split_bf16<<<(M_ * D_ / 4 + 255) / 256, 256>>>(X, (__nv_bfloat16*)pXhi,
                                                   (__nv_bfloat16*)pXlo, M_ * D_ / 4);
    split_bf16<<<(G_ * D_ / 4 + 255) / 256, 256>>>(W_ih_f, (__nv_bfloat16*)pWhi,
                                                   (__nv_bfloat16*)pWlo, G_ * D_ / 4);
    fused_main<<<FUSED_GRID, 512, FUSED_SMEM>>>(W_hh_f, b_ih_f, b_hh_f,
                                                X, W_ih_b, b_ih_b, b_hh_b);
    head_kernel<<<B_, 256>>>(W1, b1, W2, b2, W3, b3, out);
}